// round 10
// baseline (speedup 1.0000x reference)
#include <cuda_runtime.h>
#include <cuda_bf16.h>
#include <stdint.h>
#include <math.h>
#include <string.h>

// Problem constants
#define N_ROWS 65536      // B*H*W = 16*64*64
#define N_CODES 2048
#define CDIM 64
#define BM 128
#define N_TILES (N_ROWS / BM)      // 512
#define E_TILES (N_CODES / BM)     // 16
#define NCHUNK 32                  // 64-code chunks

// Output layout: concat(z_q_out[B,C,H,W], loss, perplexity, indices) as fp32
#define O_LOSS 4194304
#define O_PERP 4194305
#define O_IDX  4194306

// smem geometry: plain row-major bf16 rows (128B data) padded to 144B so
// ldmatrix 8-row phases hit distinct 4-bank groups.
#define ROWB 144
#define PLANE_A (128 * ROWB)        // 18432 B
#define PLANE_B (64 * ROWB)         // 9216 B
#define A_BYTES (3 * PLANE_A)       // 55296
#define DSMEM_REQ (A_BYTES + 6 * PLANE_B)   // 110592 -> 2 CTAs/SM

// ---------------- scratch (device globals; no allocations allowed) --------
__device__ int   g_counts[N_CODES];
__device__ float g_sumsq;

// bf16 split planes, dense row-major: uint4 index = row*8 + kgroup
__device__ uint4 g_z0[N_TILES * 1024];
__device__ uint4 g_z1[N_TILES * 1024];
__device__ uint4 g_z2[N_TILES * 1024];
__device__ uint4 g_e0[E_TILES * 1024];
__device__ uint4 g_e1[E_TILES * 1024];
__device__ uint4 g_e2[E_TILES * 1024];

// ---------------- helpers -------------------------------------------------
__device__ __forceinline__ uint32_t smem_u32(const void* p) {
    uint32_t a;
    asm("{ .reg .u64 t; cvta.to.shared.u64 t, %1; cvt.u32.u64 %0, t; }"
        : "=r"(a) : "l"(p));
    return a;
}

__device__ __forceinline__ void cp16(uint32_t dst, const void* src) {
    asm volatile("cp.async.cg.shared.global [%0], [%1], 16;"
                 :: "r"(dst), "l"(src) : "memory");
}
#define CP_COMMIT() asm volatile("cp.async.commit_group;" ::: "memory")
#define CP_WAIT1()  asm volatile("cp.async.wait_group 1;" ::: "memory")
#define CP_WAIT0()  asm volatile("cp.async.wait_group 0;" ::: "memory")

__device__ __forceinline__ void ldm4(uint32_t* r, uint32_t addr) {
    asm volatile("ldmatrix.sync.aligned.m8n8.x4.shared.b16 {%0,%1,%2,%3}, [%4];"
                 : "=r"(r[0]), "=r"(r[1]), "=r"(r[2]), "=r"(r[3]) : "r"(addr));
}

#define MMA16816(cc, a0, a1, a2, a3, bb0, bb1) \
    asm("mma.sync.aligned.m16n8k16.row.col.f32.bf16.bf16.f32 " \
        "{%0,%1,%2,%3}, {%4,%5,%6,%7}, {%8,%9}, {%0,%1,%2,%3};" \
        : "+f"((cc)[0]), "+f"((cc)[1]), "+f"((cc)[2]), "+f"((cc)[3]) \
        : "r"(a0), "r"(a1), "r"(a2), "r"(a3), "r"(bb0), "r"(bb1))

// ---------------- bf16 triple split --------------------------------------
__device__ __forceinline__ void split3(float v, unsigned short& u0,
                                       unsigned short& u1, unsigned short& u2) {
    __nv_bfloat16 h0 = __float2bfloat16(v);
    float r1 = v - __bfloat162float(h0);
    __nv_bfloat16 h1 = __float2bfloat16(r1);
    float r2 = r1 - __bfloat162float(h1);
    __nv_bfloat16 h2 = __float2bfloat16(r2);
    memcpy(&u0, &h0, 2); memcpy(&u1, &h1, 2); memcpy(&u2, &h2, 2);
}
__device__ __forceinline__ uint32_t pack2(unsigned short lo, unsigned short hi) {
    return (uint32_t)lo | ((uint32_t)hi << 16);
}

// ---------------- kernel: split z (plain row-major) ----------------------
__global__ void __launch_bounds__(128)
vq_split_z(const float* __restrict__ z) {
    __shared__ float s[64][129];
    const int tile = blockIdx.x;
    const int n0 = tile * BM;
    const int b = n0 >> 12, p0 = n0 & 4095;
    const float* src = z + ((size_t)b * CDIM) * 4096 + p0;
    const int i = threadIdx.x;
#pragma unroll 8
    for (int c = 0; c < 64; c++) s[c][i] = src[(size_t)c * 4096 + i];
    __syncthreads();

#pragma unroll
    for (int j = 0; j < 8; j++) {
        unsigned short u0[8], u1[8], u2[8];
#pragma unroll
        for (int q = 0; q < 8; q++) split3(s[j * 8 + q][i], u0[q], u1[q], u2[q]);
        int idx = tile * 1024 + i * 8 + j;
        g_z0[idx] = make_uint4(pack2(u0[0], u0[1]), pack2(u0[2], u0[3]),
                               pack2(u0[4], u0[5]), pack2(u0[6], u0[7]));
        g_z1[idx] = make_uint4(pack2(u1[0], u1[1]), pack2(u1[2], u1[3]),
                               pack2(u1[4], u1[5]), pack2(u1[6], u1[7]));
        g_z2[idx] = make_uint4(pack2(u2[0], u2[1]), pack2(u2[2], u2[3]),
                               pack2(u2[4], u2[5]), pack2(u2[6], u2[7]));
    }
}

// ---------------- kernel: split codebook (plain row-major) ---------------
__global__ void __launch_bounds__(128)
vq_split_cb(const float* __restrict__ cb) {
    const int tile = blockIdx.x;
    const int i = threadIdx.x;
    float v[64];
    const float4* src = (const float4*)(cb + (size_t)(tile * BM + i) * CDIM);
#pragma unroll
    for (int t = 0; t < 16; t++) {
        float4 x = src[t];
        v[t * 4] = x.x; v[t * 4 + 1] = x.y; v[t * 4 + 2] = x.z; v[t * 4 + 3] = x.w;
    }
#pragma unroll
    for (int j = 0; j < 8; j++) {
        unsigned short u0[8], u1[8], u2[8];
#pragma unroll
        for (int q = 0; q < 8; q++) split3(v[j * 8 + q], u0[q], u1[q], u2[q]);
        int idx = tile * 1024 + i * 8 + j;
        g_e0[idx] = make_uint4(pack2(u0[0], u0[1]), pack2(u0[2], u0[3]),
                               pack2(u0[4], u0[5]), pack2(u0[6], u0[7]));
        g_e1[idx] = make_uint4(pack2(u1[0], u1[1]), pack2(u1[2], u1[3]),
                               pack2(u1[4], u1[5]), pack2(u1[6], u1[7]));
        g_e2[idx] = make_uint4(pack2(u2[0], u2[1]), pack2(u2[2], u2[3]),
                               pack2(u2[4], u2[5]), pack2(u2[6], u2[7]));
    }
}

__global__ void vq_init() {
    for (int i = threadIdx.x; i < N_CODES; i += blockDim.x) g_counts[i] = 0;
    if (threadIdx.x == 0) g_sumsq = 0.0f;
}

// ---------------- kernel: mma.sync GEMM + argmax + fused epilogue --------
// Emulated fp32 via bf16x3: logits = z0e0+z0e1+z1e0+z1e1+z0e2+z2e0, single
// accumulator set. 8 warps, warp tile 64x16, 64-code chunks, 2 CTAs/SM.
// MMA issue order is B-plane-outer so same-accumulator MMAs are 8 apart.
// Epilogue: gather cb[idx], loss vs zp (reconstructed from smem planes),
// histogram, transposed z_q store — vq_gather kernel eliminated.
__global__ void __launch_bounds__(256, 2)
vq_mma(const float* __restrict__ cbf, float* __restrict__ out) {
    extern __shared__ char dsm[];
    const int tid = threadIdx.x;
    const int w = tid >> 5, lane = tid & 31;
    const int g = lane >> 2, q = lane & 3;
    const int mrow = lane & 7, quad = lane >> 3;
    const int wm = (w & 1) * 64, wn = (w >> 1) * 16;
    const int tile = blockIdx.x;

    const uint32_t sA = smem_u32(dsm);
    const uint32_t sB = sA + A_BYTES;

    // ldmatrix per-thread intra-plane offsets
    const uint32_t aoff = (uint32_t)(wm + mrow + 8 * (quad & 1)) * ROWB
                        + 16 * (quad >> 1);
    const uint32_t boff = (uint32_t)(wn + mrow + 8 * (quad >> 1)) * ROWB
                        + 16 * (quad & 1);

    // prologue: A tiles + B chunk 0 (one commit group)
    {
        const uint4* zs[3] = {g_z0 + tile * 1024, g_z1 + tile * 1024,
                              g_z2 + tile * 1024};
        for (int t = tid; t < 3072; t += 256) {
            int pl = t >> 10, rem = t & 1023, r = rem >> 3, j = rem & 7;
            cp16(sA + pl * PLANE_A + r * ROWB + j * 16, zs[pl] + rem);
        }
        const uint4* es[3] = {g_e0, g_e1, g_e2};
        for (int t = tid; t < 1536; t += 256) {
            int pl = t >> 9, rem = t & 511, r = rem >> 3, j = rem & 7;
            cp16(sB + pl * PLANE_B + r * ROWB + j * 16, es[pl] + rem);
        }
        CP_COMMIT();
    }

    float bv[8];
    int   bi[8];
#pragma unroll
    for (int e = 0; e < 8; e++) { bv[e] = -3.4e38f; bi[e] = 0; }

    for (int ch = 0; ch < NCHUNK; ch++) {
        if (ch < NCHUNK - 1) {   // prefetch next B chunk into other buffer
            const uint4* es[3] = {g_e0 + (ch + 1) * 512, g_e1 + (ch + 1) * 512,
                                  g_e2 + (ch + 1) * 512};
            uint32_t dstb = sB + ((ch + 1) & 1) * (3 * PLANE_B);
            for (int t = tid; t < 1536; t += 256) {
                int pl = t >> 9, rem = t & 511, r = rem >> 3, j = rem & 7;
                cp16(dstb + pl * PLANE_B + r * ROWB + j * 16, es[pl] + rem);
            }
            CP_COMMIT();
            CP_WAIT1();
        } else {
            CP_WAIT0();
        }
        __syncthreads();

        const uint32_t bB = sB + (ch & 1) * (3 * PLANE_B);

        float c[4][2][4];
#pragma unroll
        for (int mi = 0; mi < 4; mi++)
#pragma unroll
            for (int ni = 0; ni < 2; ni++)
#pragma unroll
                for (int e = 0; e < 4; e++) c[mi][ni][e] = 0.0f;

#pragma unroll
        for (int ks = 0; ks < 4; ks++) {
            const uint32_t koff = ks * 32;
            uint32_t B0[4], B1[4], B2[4];
            ldm4(B0, bB + 0 * PLANE_B + boff + koff);
            ldm4(B1, bB + 1 * PLANE_B + boff + koff);
            ldm4(B2, bB + 2 * PLANE_B + boff + koff);

            uint32_t A[16];
            // z0: products with e0, e1, e2 (B-plane-outer: RAW distance 8)
            ldm4(A,      sA + 0 * PLANE_A + aoff + koff);
            ldm4(A + 4,  sA + 0 * PLANE_A + aoff + koff + 16 * ROWB);
            ldm4(A + 8,  sA + 0 * PLANE_A + aoff + koff + 32 * ROWB);
            ldm4(A + 12, sA + 0 * PLANE_A + aoff + koff + 48 * ROWB);
#pragma unroll
            for (int mi = 0; mi < 4; mi++)
#pragma unroll
                for (int ni = 0; ni < 2; ni++)
                    MMA16816(c[mi][ni], A[mi*4], A[mi*4+1], A[mi*4+2], A[mi*4+3],
                             B0[ni*2], B0[ni*2+1]);
#pragma unroll
            for (int mi = 0; mi < 4; mi++)
#pragma unroll
                for (int ni = 0; ni < 2; ni++)
                    MMA16816(c[mi][ni], A[mi*4], A[mi*4+1], A[mi*4+2], A[mi*4+3],
                             B1[ni*2], B1[ni*2+1]);
#pragma unroll
            for (int mi = 0; mi < 4; mi++)
#pragma unroll
                for (int ni = 0; ni < 2; ni++)
                    MMA16816(c[mi][ni], A[mi*4], A[mi*4+1], A[mi*4+2], A[mi*4+3],
                             B2[ni*2], B2[ni*2+1]);
            // z1: products with e0, e1
            ldm4(A,      sA + 1 * PLANE_A + aoff + koff);
            ldm4(A + 4,  sA + 1 * PLANE_A + aoff + koff + 16 * ROWB);
            ldm4(A + 8,  sA + 1 * PLANE_A + aoff + koff + 32 * ROWB);
            ldm4(A + 12, sA + 1 * PLANE_A + aoff + koff + 48 * ROWB);
#pragma unroll
            for (int mi = 0; mi < 4; mi++)
#pragma unroll
                for (int ni = 0; ni < 2; ni++)
                    MMA16816(c[mi][ni], A[mi*4], A[mi*4+1], A[mi*4+2], A[mi*4+3],
                             B0[ni*2], B0[ni*2+1]);
#pragma unroll
            for (int mi = 0; mi < 4; mi++)
#pragma unroll
                for (int ni = 0; ni < 2; ni++)
                    MMA16816(c[mi][ni], A[mi*4], A[mi*4+1], A[mi*4+2], A[mi*4+3],
                             B1[ni*2], B1[ni*2+1]);
            // z2: product with e0
            ldm4(A,      sA + 2 * PLANE_A + aoff + koff);
            ldm4(A + 4,  sA + 2 * PLANE_A + aoff + koff + 16 * ROWB);
            ldm4(A + 8,  sA + 2 * PLANE_A + aoff + koff + 32 * ROWB);
            ldm4(A + 12, sA + 2 * PLANE_A + aoff + koff + 48 * ROWB);
#pragma unroll
            for (int mi = 0; mi < 4; mi++)
#pragma unroll
                for (int ni = 0; ni < 2; ni++)
                    MMA16816(c[mi][ni], A[mi*4], A[mi*4+1], A[mi*4+2], A[mi*4+3],
                             B0[ni*2], B0[ni*2+1]);
        }

        // fold chunk into running argmax (ascending candidate order -> strict >)
        const int cb0 = ch * 64 + wn + 2 * q;
#pragma unroll
        for (int mi = 0; mi < 4; mi++) {
            const int lo = mi * 2, hi = mi * 2 + 1;
#pragma unroll
            for (int ni = 0; ni < 2; ni++) {
                int ce = cb0 + 8 * ni;
                if (c[mi][ni][0] > bv[lo]) { bv[lo] = c[mi][ni][0]; bi[lo] = ce; }
                if (c[mi][ni][1] > bv[lo]) { bv[lo] = c[mi][ni][1]; bi[lo] = ce + 1; }
                if (c[mi][ni][2] > bv[hi]) { bv[hi] = c[mi][ni][2]; bi[hi] = ce; }
                if (c[mi][ni][3] > bv[hi]) { bv[hi] = c[mi][ni][3]; bi[hi] = ce + 1; }
            }
        }
        __syncthreads();
    }

    // quad shuffle reduce (lanes sharing a row differ only in q)
#pragma unroll
    for (int e = 0; e < 8; e++) {
#pragma unroll
        for (int off = 1; off <= 2; off <<= 1) {
            float ov = __shfl_xor_sync(0xffffffffu, bv[e], off);
            int   oi = __shfl_xor_sync(0xffffffffu, bi[e], off);
            if (ov > bv[e] || (ov == bv[e] && oi < bi[e])) { bv[e] = ov; bi[e] = oi; }
        }
    }

    // reductions staged in dead B region (A planes still needed for zp)
    float* sval = (float*)(dsm + A_BYTES);             // [128][4]
    int*   sidx = (int*)(dsm + A_BYTES + 2048);        // [128][4]
    int*   ids  = (int*)(dsm + A_BYTES + 4096);        // [128]
    float* wsum = (float*)(dsm + A_BYTES + 4608);      // [8]
    float* zq   = (float*)(dsm + A_BYTES + 8192);      // [128][65]
    if (q == 0) {
#pragma unroll
        for (int e = 0; e < 8; e++) {
            int r = wm + 16 * (e >> 1) + 8 * (e & 1) + g;
            sval[r * 4 + (w >> 1)] = bv[e];
            sidx[r * 4 + (w >> 1)] = bi[e];
        }
    }
    __syncthreads();
    if (tid < 128) {
        float v = sval[tid * 4];
        int   i2 = sidx[tid * 4];
#pragma unroll
        for (int wg = 1; wg < 4; wg++) {
            float ov = sval[tid * 4 + wg];
            int   oi = sidx[tid * 4 + wg];
            if (ov > v || (ov == v && oi < i2)) { v = ov; i2 = oi; }
        }
        int n = tile * BM + tid;
        ids[tid] = i2;
        out[O_IDX + n] = (float)i2;
        atomicAdd(&g_counts[i2], 1);
    }
    __syncthreads();

    // gather codebook rows (fp32, L2-resident) into staging
    {
        int row = tid >> 1, h = tid & 1;
        const float4* src = (const float4*)(cbf + (size_t)ids[row] * CDIM + h * 32);
#pragma unroll
        for (int t = 0; t < 8; t++) {
            float4 vv = src[t];
            int c = h * 32 + t * 4;
            zq[row * 65 + c]     = vv.x;
            zq[row * 65 + c + 1] = vv.y;
            zq[row * 65 + c + 2] = vv.z;
            zq[row * 65 + c + 3] = vv.w;
        }
    }
    __syncthreads();

    // loss + transposed coalesced z_q store; zp = z0+z1+z2 from smem planes
    {
        const int i = tid & 127;
        const int c0 = tid >> 7;
        const int b  = tile >> 5;
        const int p0 = (tile & 31) * BM;
        float* od = out + ((size_t)b * CDIM) * 4096 + p0;
        const char* a0 = dsm + 0 * PLANE_A + i * ROWB;
        const char* a1 = dsm + 1 * PLANE_A + i * ROWB;
        const char* a2 = dsm + 2 * PLANE_A + i * ROWB;
        float lsum = 0.0f;
#pragma unroll
        for (int s = 0; s < 32; s++) {
            int c = c0 + 2 * s;
            float zp = __bfloat162float(*(const __nv_bfloat16*)(a0 + 2 * c))
                     + __bfloat162float(*(const __nv_bfloat16*)(a1 + 2 * c))
                     + __bfloat162float(*(const __nv_bfloat16*)(a2 + 2 * c));
            float vq = zq[i * 65 + c];
            float d = vq - zp;
            lsum += d * d;
            od[(size_t)c * 4096 + i] = vq;
        }
        for (int o = 16; o > 0; o >>= 1)
            lsum += __shfl_down_sync(0xffffffffu, lsum, o);
        if (lane == 0) wsum[w] = lsum;
        __syncthreads();
        if (tid == 0) {
            float t = 0.0f;
#pragma unroll
            for (int ww = 0; ww < 8; ww++) t += wsum[ww];
            atomicAdd(&g_sumsq, t);
        }
    }
}

// ---------------- kernel: scalars ----------------------------------------
__global__ void vq_final(float* __restrict__ out) {
    __shared__ float red[256];
    const int tid = threadIdx.x;
    float h = 0.0f;
    for (int i = tid; i < N_CODES; i += 256) {
        float e = (float)g_counts[i] * (1.0f / 65536.0f);
        h -= e * logf(e + 1e-10f);
    }
    red[tid] = h;
    __syncthreads();
    for (int o = 128; o > 0; o >>= 1) {
        if (tid < o) red[tid] += red[tid + o];
        __syncthreads();
    }
    if (tid == 0) {
        out[O_LOSS] = 1.25f * g_sumsq / 4194304.0f;
        out[O_PERP] = expf(red[0]);
    }
}

extern "C" void kernel_launch(void* const* d_in, const int* in_sizes, int n_in,
                              void* d_out, int out_size) {
    const float* z  = (const float*)d_in[0];
    const float* cb = (const float*)d_in[1];
    if (n_in >= 2 && in_sizes[0] == N_CODES * CDIM) {
        z  = (const float*)d_in[1];
        cb = (const float*)d_in[0];
    }
    float* out = (float*)d_out;

    cudaFuncSetAttribute(vq_mma, cudaFuncAttributeMaxDynamicSharedMemorySize,
                         DSMEM_REQ);

    vq_split_z<<<N_TILES, 128>>>(z);
    vq_split_cb<<<E_TILES, 128>>>(cb);
    vq_init<<<1, 256>>>();
    vq_mma<<<N_TILES, 256, DSMEM_REQ>>>(cb, out);
    vq_final<<<1, 256>>>(out);
    (void)out_size;
}

// round 12
// speedup vs baseline: 1.0494x; 1.0494x over previous
#include <cuda_runtime.h>
#include <cuda_bf16.h>
#include <stdint.h>
#include <math.h>
#include <string.h>

// Problem constants
#define N_ROWS 65536      // B*H*W = 16*64*64
#define N_CODES 2048
#define CDIM 64
#define BM 128
#define N_TILES (N_ROWS / BM)      // 512
#define E_TILES (N_CODES / BM)     // 16
#define NCHUNK 32                  // 64-code chunks

// Output layout: concat(z_q_out[B,C,H,W], loss, perplexity, indices) as fp32
#define O_LOSS 4194304
#define O_PERP 4194305
#define O_IDX  4194306

// smem geometry: plain row-major bf16 rows (128B data) padded to 144B so
// ldmatrix 8-row phases hit distinct 4-bank groups.
#define ROWB 144
#define PLANE_A (128 * ROWB)        // 18432 B
#define PLANE_B (64 * ROWB)         // 9216 B
#define A_BYTES (3 * PLANE_A)       // 55296
#define DSMEM_REQ (A_BYTES + 6 * PLANE_B)   // 110592 -> 2 CTAs/SM

// ---------------- scratch (device globals; no allocations allowed) --------
__device__ int   g_counts[N_CODES];
__device__ float g_sumsq;

// bf16 split planes, dense row-major: uint4 index = row*8 + kgroup
__device__ uint4 g_z0[N_TILES * 1024];
__device__ uint4 g_z1[N_TILES * 1024];
__device__ uint4 g_z2[N_TILES * 1024];
__device__ uint4 g_e0[E_TILES * 1024];
__device__ uint4 g_e1[E_TILES * 1024];
__device__ uint4 g_e2[E_TILES * 1024];

// ---------------- helpers -------------------------------------------------
__device__ __forceinline__ uint32_t smem_u32(const void* p) {
    uint32_t a;
    asm("{ .reg .u64 t; cvta.to.shared.u64 t, %1; cvt.u32.u64 %0, t; }"
        : "=r"(a) : "l"(p));
    return a;
}

__device__ __forceinline__ void cp16(uint32_t dst, const void* src) {
    asm volatile("cp.async.cg.shared.global [%0], [%1], 16;"
                 :: "r"(dst), "l"(src) : "memory");
}
#define CP_COMMIT() asm volatile("cp.async.commit_group;" ::: "memory")
#define CP_WAIT1()  asm volatile("cp.async.wait_group 1;" ::: "memory")
#define CP_WAIT0()  asm volatile("cp.async.wait_group 0;" ::: "memory")

__device__ __forceinline__ void ldm4(uint32_t* r, uint32_t addr) {
    asm volatile("ldmatrix.sync.aligned.m8n8.x4.shared.b16 {%0,%1,%2,%3}, [%4];"
                 : "=r"(r[0]), "=r"(r[1]), "=r"(r[2]), "=r"(r[3]) : "r"(addr));
}

#define MMA16816(cc, a0, a1, a2, a3, bb0, bb1) \
    asm("mma.sync.aligned.m16n8k16.row.col.f32.bf16.bf16.f32 " \
        "{%0,%1,%2,%3}, {%4,%5,%6,%7}, {%8,%9}, {%0,%1,%2,%3};" \
        : "+f"((cc)[0]), "+f"((cc)[1]), "+f"((cc)[2]), "+f"((cc)[3]) \
        : "r"(a0), "r"(a1), "r"(a2), "r"(a3), "r"(bb0), "r"(bb1))

// ---------------- bf16 triple split --------------------------------------
__device__ __forceinline__ void split3(float v, unsigned short& u0,
                                       unsigned short& u1, unsigned short& u2) {
    __nv_bfloat16 h0 = __float2bfloat16(v);
    float r1 = v - __bfloat162float(h0);
    __nv_bfloat16 h1 = __float2bfloat16(r1);
    float r2 = r1 - __bfloat162float(h1);
    __nv_bfloat16 h2 = __float2bfloat16(r2);
    memcpy(&u0, &h0, 2); memcpy(&u1, &h1, 2); memcpy(&u2, &h2, 2);
}
__device__ __forceinline__ uint32_t pack2(unsigned short lo, unsigned short hi) {
    return (uint32_t)lo | ((uint32_t)hi << 16);
}

// ---------------- kernel: split z (plain row-major) ----------------------
__global__ void __launch_bounds__(128)
vq_split_z(const float* __restrict__ z) {
    __shared__ float s[64][129];
    const int tile = blockIdx.x;
    const int n0 = tile * BM;
    const int b = n0 >> 12, p0 = n0 & 4095;
    const float* src = z + ((size_t)b * CDIM) * 4096 + p0;
    const int i = threadIdx.x;
#pragma unroll 8
    for (int c = 0; c < 64; c++) s[c][i] = src[(size_t)c * 4096 + i];
    __syncthreads();

#pragma unroll
    for (int j = 0; j < 8; j++) {
        unsigned short u0[8], u1[8], u2[8];
#pragma unroll
        for (int q = 0; q < 8; q++) split3(s[j * 8 + q][i], u0[q], u1[q], u2[q]);
        int idx = tile * 1024 + i * 8 + j;
        g_z0[idx] = make_uint4(pack2(u0[0], u0[1]), pack2(u0[2], u0[3]),
                               pack2(u0[4], u0[5]), pack2(u0[6], u0[7]));
        g_z1[idx] = make_uint4(pack2(u1[0], u1[1]), pack2(u1[2], u1[3]),
                               pack2(u1[4], u1[5]), pack2(u1[6], u1[7]));
        g_z2[idx] = make_uint4(pack2(u2[0], u2[1]), pack2(u2[2], u2[3]),
                               pack2(u2[4], u2[5]), pack2(u2[6], u2[7]));
    }
}

// ---------------- kernel: split codebook (plain row-major) ---------------
__global__ void __launch_bounds__(128)
vq_split_cb(const float* __restrict__ cb) {
    const int tile = blockIdx.x;
    const int i = threadIdx.x;
    float v[64];
    const float4* src = (const float4*)(cb + (size_t)(tile * BM + i) * CDIM);
#pragma unroll
    for (int t = 0; t < 16; t++) {
        float4 x = src[t];
        v[t * 4] = x.x; v[t * 4 + 1] = x.y; v[t * 4 + 2] = x.z; v[t * 4 + 3] = x.w;
    }
#pragma unroll
    for (int j = 0; j < 8; j++) {
        unsigned short u0[8], u1[8], u2[8];
#pragma unroll
        for (int q = 0; q < 8; q++) split3(v[j * 8 + q], u0[q], u1[q], u2[q]);
        int idx = tile * 1024 + i * 8 + j;
        g_e0[idx] = make_uint4(pack2(u0[0], u0[1]), pack2(u0[2], u0[3]),
                               pack2(u0[4], u0[5]), pack2(u0[6], u0[7]));
        g_e1[idx] = make_uint4(pack2(u1[0], u1[1]), pack2(u1[2], u1[3]),
                               pack2(u1[4], u1[5]), pack2(u1[6], u1[7]));
        g_e2[idx] = make_uint4(pack2(u2[0], u2[1]), pack2(u2[2], u2[3]),
                               pack2(u2[4], u2[5]), pack2(u2[6], u2[7]));
    }
}

__global__ void vq_init() {
    for (int i = threadIdx.x; i < N_CODES; i += blockDim.x) g_counts[i] = 0;
    if (threadIdx.x == 0) g_sumsq = 0.0f;
}

// ---------------- kernel: mma.sync GEMM + argmax + fused epilogue --------
// Emulated fp32 via bf16x3: logits = z0e0+z0e1+z1e0+z1e1+z0e2+z2e0, single
// accumulator set. 16 warps of 512 threads, warp tile 32x16 (4m x 4n grid),
// 64-code chunks, 2 CTAs/SM -> 8 warps/SMSP for latency hiding.
__global__ void __launch_bounds__(512, 2)
vq_mma(const float* __restrict__ cbf, float* __restrict__ out) {
    extern __shared__ char dsm[];
    const int tid = threadIdx.x;
    const int w = tid >> 5, lane = tid & 31;
    const int g = lane >> 2, q = lane & 3;
    const int mrow = lane & 7, quad = lane >> 3;
    const int wm = (w & 3) * 32, wn = (w >> 2) * 16;
    const int tile = blockIdx.x;

    const uint32_t sA = smem_u32(dsm);
    const uint32_t sB = sA + A_BYTES;

    // ldmatrix per-thread intra-plane offsets
    const uint32_t aoff = (uint32_t)(wm + mrow + 8 * (quad & 1)) * ROWB
                        + 16 * (quad >> 1);
    const uint32_t boff = (uint32_t)(wn + mrow + 8 * (quad >> 1)) * ROWB
                        + 16 * (quad & 1);

    // prologue: A tiles + B chunk 0 (one commit group)
    {
        const uint4* zs[3] = {g_z0 + tile * 1024, g_z1 + tile * 1024,
                              g_z2 + tile * 1024};
        for (int t = tid; t < 3072; t += 512) {
            int pl = t >> 10, rem = t & 1023, r = rem >> 3, j = rem & 7;
            cp16(sA + pl * PLANE_A + r * ROWB + j * 16, zs[pl] + rem);
        }
        const uint4* es[3] = {g_e0, g_e1, g_e2};
        for (int t = tid; t < 1536; t += 512) {
            int pl = t >> 9, rem = t & 511, r = rem >> 3, j = rem & 7;
            cp16(sB + pl * PLANE_B + r * ROWB + j * 16, es[pl] + rem);
        }
        CP_COMMIT();
    }

    float bv[4];
    int   bi[4];
#pragma unroll
    for (int e = 0; e < 4; e++) { bv[e] = -3.4e38f; bi[e] = 0; }

    for (int ch = 0; ch < NCHUNK; ch++) {
        if (ch < NCHUNK - 1) {   // prefetch next B chunk into other buffer
            const uint4* es[3] = {g_e0 + (ch + 1) * 512, g_e1 + (ch + 1) * 512,
                                  g_e2 + (ch + 1) * 512};
            uint32_t dstb = sB + ((ch + 1) & 1) * (3 * PLANE_B);
            for (int t = tid; t < 1536; t += 512) {
                int pl = t >> 9, rem = t & 511, r = rem >> 3, j = rem & 7;
                cp16(dstb + pl * PLANE_B + r * ROWB + j * 16, es[pl] + rem);
            }
            CP_COMMIT();
            CP_WAIT1();
        } else {
            CP_WAIT0();
        }
        __syncthreads();

        const uint32_t bB = sB + (ch & 1) * (3 * PLANE_B);

        float c[2][2][4];
#pragma unroll
        for (int mi = 0; mi < 2; mi++)
#pragma unroll
            for (int ni = 0; ni < 2; ni++)
#pragma unroll
                for (int e = 0; e < 4; e++) c[mi][ni][e] = 0.0f;

#pragma unroll
        for (int ks = 0; ks < 4; ks++) {
            const uint32_t koff = ks * 32;
            uint32_t B0[4], B1[4], B2[4];
            ldm4(B0, bB + 0 * PLANE_B + boff + koff);
            ldm4(B1, bB + 1 * PLANE_B + boff + koff);
            ldm4(B2, bB + 2 * PLANE_B + boff + koff);

            uint32_t A[8];
            // z0: products with e0, e1, e2 (R9 interleaved order)
            ldm4(A,     sA + 0 * PLANE_A + aoff + koff);
            ldm4(A + 4, sA + 0 * PLANE_A + aoff + koff + 16 * ROWB);
#pragma unroll
            for (int mi = 0; mi < 2; mi++)
#pragma unroll
                for (int ni = 0; ni < 2; ni++) {
                    MMA16816(c[mi][ni], A[mi*4], A[mi*4+1], A[mi*4+2], A[mi*4+3],
                             B0[ni*2], B0[ni*2+1]);
                    MMA16816(c[mi][ni], A[mi*4], A[mi*4+1], A[mi*4+2], A[mi*4+3],
                             B1[ni*2], B1[ni*2+1]);
                    MMA16816(c[mi][ni], A[mi*4], A[mi*4+1], A[mi*4+2], A[mi*4+3],
                             B2[ni*2], B2[ni*2+1]);
                }
            // z1: products with e0, e1
            ldm4(A,     sA + 1 * PLANE_A + aoff + koff);
            ldm4(A + 4, sA + 1 * PLANE_A + aoff + koff + 16 * ROWB);
#pragma unroll
            for (int mi = 0; mi < 2; mi++)
#pragma unroll
                for (int ni = 0; ni < 2; ni++) {
                    MMA16816(c[mi][ni], A[mi*4], A[mi*4+1], A[mi*4+2], A[mi*4+3],
                             B0[ni*2], B0[ni*2+1]);
                    MMA16816(c[mi][ni], A[mi*4], A[mi*4+1], A[mi*4+2], A[mi*4+3],
                             B1[ni*2], B1[ni*2+1]);
                }
            // z2: product with e0
            ldm4(A,     sA + 2 * PLANE_A + aoff + koff);
            ldm4(A + 4, sA + 2 * PLANE_A + aoff + koff + 16 * ROWB);
#pragma unroll
            for (int mi = 0; mi < 2; mi++)
#pragma unroll
                for (int ni = 0; ni < 2; ni++)
                    MMA16816(c[mi][ni], A[mi*4], A[mi*4+1], A[mi*4+2], A[mi*4+3],
                             B0[ni*2], B0[ni*2+1]);
        }

        // fold chunk into running argmax (ascending candidate order -> strict >)
        const int cb0 = ch * 64 + wn + 2 * q;
#pragma unroll
        for (int mi = 0; mi < 2; mi++) {
            const int lo = mi * 2, hi = mi * 2 + 1;
#pragma unroll
            for (int ni = 0; ni < 2; ni++) {
                int ce = cb0 + 8 * ni;
                if (c[mi][ni][0] > bv[lo]) { bv[lo] = c[mi][ni][0]; bi[lo] = ce; }
                if (c[mi][ni][1] > bv[lo]) { bv[lo] = c[mi][ni][1]; bi[lo] = ce + 1; }
                if (c[mi][ni][2] > bv[hi]) { bv[hi] = c[mi][ni][2]; bi[hi] = ce; }
                if (c[mi][ni][3] > bv[hi]) { bv[hi] = c[mi][ni][3]; bi[hi] = ce + 1; }
            }
        }
        __syncthreads();
    }

    // quad shuffle reduce (lanes sharing a row differ only in q)
#pragma unroll
    for (int e = 0; e < 4; e++) {
#pragma unroll
        for (int off = 1; off <= 2; off <<= 1) {
            float ov = __shfl_xor_sync(0xffffffffu, bv[e], off);
            int   oi = __shfl_xor_sync(0xffffffffu, bi[e], off);
            if (ov > bv[e] || (ov == bv[e] && oi < bi[e])) { bv[e] = ov; bi[e] = oi; }
        }
    }

    // reductions staged in dead B region (A planes still needed for zp)
    float* sval = (float*)(dsm + A_BYTES);             // [128][4]
    int*   sidx = (int*)(dsm + A_BYTES + 2048);        // [128][4]
    int*   ids  = (int*)(dsm + A_BYTES + 4096);        // [128]
    float* wsum = (float*)(dsm + A_BYTES + 4608);      // [16]
    float* zq   = (float*)(dsm + A_BYTES + 8192);      // [128][65]
    if (q == 0) {
#pragma unroll
        for (int mi = 0; mi < 2; mi++)
#pragma unroll
            for (int h = 0; h < 2; h++) {
                int r = wm + 16 * mi + 8 * h + g;
                sval[r * 4 + (w >> 2)] = bv[mi * 2 + h];
                sidx[r * 4 + (w >> 2)] = bi[mi * 2 + h];
            }
    }
    __syncthreads();
    if (tid < 128) {
        float v = sval[tid * 4];
        int   i2 = sidx[tid * 4];
#pragma unroll
        for (int wg = 1; wg < 4; wg++) {
            float ov = sval[tid * 4 + wg];
            int   oi = sidx[tid * 4 + wg];
            if (ov > v || (ov == v && oi < i2)) { v = ov; i2 = oi; }
        }
        int n = tile * BM + tid;
        ids[tid] = i2;
        out[O_IDX + n] = (float)i2;
        atomicAdd(&g_counts[i2], 1);
    }
    __syncthreads();

    // gather codebook rows (fp32, L2-resident) into staging
    {
        int row = tid >> 2, h = tid & 3;
        const float4* src = (const float4*)(cbf + (size_t)ids[row] * CDIM + h * 16);
#pragma unroll
        for (int t = 0; t < 4; t++) {
            float4 vv = src[t];
            int c = h * 16 + t * 4;
            zq[row * 65 + c]     = vv.x;
            zq[row * 65 + c + 1] = vv.y;
            zq[row * 65 + c + 2] = vv.z;
            zq[row * 65 + c + 3] = vv.w;
        }
    }
    __syncthreads();

    // loss + transposed coalesced z_q store; zp = z0+z1+z2 from smem planes
    {
        const int i = tid & 127;
        const int c0 = tid >> 7;          // 0..3
        const int b  = tile >> 5;
        const int p0 = (tile & 31) * BM;
        float* od = out + ((size_t)b * CDIM) * 4096 + p0;
        const char* a0 = dsm + 0 * PLANE_A + i * ROWB;
        const char* a1 = dsm + 1 * PLANE_A + i * ROWB;
        const char* a2 = dsm + 2 * PLANE_A + i * ROWB;
        float lsum = 0.0f;
#pragma unroll
        for (int s = 0; s < 16; s++) {
            int c = c0 + 4 * s;
            float zp = __bfloat162float(*(const __nv_bfloat16*)(a0 + 2 * c))
                     + __bfloat162float(*(const __nv_bfloat16*)(a1 + 2 * c))
                     + __bfloat162float(*(const __nv_bfloat16*)(a2 + 2 * c));
            float vq = zq[i * 65 + c];
            float d = vq - zp;
            lsum += d * d;
            od[(size_t)c * 4096 + i] = vq;
        }
        for (int o = 16; o > 0; o >>= 1)
            lsum += __shfl_down_sync(0xffffffffu, lsum, o);
        if (lane == 0) wsum[w] = lsum;
        __syncthreads();
        if (tid == 0) {
            float t = 0.0f;
#pragma unroll
            for (int ww = 0; ww < 16; ww++) t += wsum[ww];
            atomicAdd(&g_sumsq, t);
        }
    }
}

// ---------------- kernel: scalars ----------------------------------------
__global__ void vq_final(float* __restrict__ out) {
    __shared__ float red[256];
    const int tid = threadIdx.x;
    float h = 0.0f;
    for (int i = tid; i < N_CODES; i += 256) {
        float e = (float)g_counts[i] * (1.0f / 65536.0f);
        h -= e * logf(e + 1e-10f);
    }
    red[tid] = h;
    __syncthreads();
    for (int o = 128; o > 0; o >>= 1) {
        if (tid < o) red[tid] += red[tid + o];
        __syncthreads();
    }
    if (tid == 0) {
        out[O_LOSS] = 1.25f * g_sumsq / 4194304.0f;
        out[O_PERP] = expf(red[0]);
    }
}

extern "C" void kernel_launch(void* const* d_in, const int* in_sizes, int n_in,
                              void* d_out, int out_size) {
    const float* z  = (const float*)d_in[0];
    const float* cb = (const float*)d_in[1];
    if (n_in >= 2 && in_sizes[0] == N_CODES * CDIM) {
        z  = (const float*)d_in[1];
        cb = (const float*)d_in[0];
    }
    float* out = (float*)d_out;

    cudaFuncSetAttribute(vq_mma, cudaFuncAttributeMaxDynamicSharedMemorySize,
                         DSMEM_REQ);

    vq_split_z<<<N_TILES, 128>>>(z);
    vq_split_cb<<<E_TILES, 128>>>(cb);
    vq_init<<<1, 256>>>();
    vq_mma<<<N_TILES, 512, DSMEM_REQ>>>(cb, out);
    vq_final<<<1, 256>>>(out);
    (void)out_size;
}

// round 13
// speedup vs baseline: 1.4636x; 1.3947x over previous
#include <cuda_runtime.h>
#include <cuda_fp16.h>
#include <stdint.h>
#include <math.h>
#include <string.h>

// Problem constants
#define N_ROWS 65536      // B*H*W = 16*64*64
#define N_CODES 2048
#define CDIM 64
#define BM 128
#define N_TILES (N_ROWS / BM)      // 512
#define E_TILES (N_CODES / BM)     // 16
#define NCHUNK 32                  // 64-code chunks

// Output layout: concat(z_q_out[B,C,H,W], loss, perplexity, indices) as fp32
#define O_LOSS 4194304
#define O_PERP 4194305
#define O_IDX  4194306

// smem geometry: plain row-major fp16 rows (128B data) padded to 144B so
// ldmatrix 8-row phases hit distinct 4-bank groups.
#define ROWB 144
#define PLANE_A (128 * ROWB)        // 18432 B
#define PLANE_B (64 * ROWB)         // 9216 B
#define A_BYTES (2 * PLANE_A)       // 36864 (2 fp16 planes)
// data need: A 36864 + B 2x2 planes 36864 = 73728; epilogue staging to 74816.
// padded to 78336 so exactly 2 CTAs/SM (3x78336 > 228KB carveout).
#define DSMEM_REQ 78336

// ---------------- scratch (device globals; no allocations allowed) --------
__device__ int   g_counts[N_CODES];
__device__ float g_sumsq;

// fp16 split planes, dense row-major: uint4 index = row*8 + kgroup
__device__ uint4 g_z0[N_TILES * 1024];
__device__ uint4 g_z1[N_TILES * 1024];
__device__ uint4 g_e0[E_TILES * 1024];
__device__ uint4 g_e1[E_TILES * 1024];

// ---------------- helpers -------------------------------------------------
__device__ __forceinline__ uint32_t smem_u32(const void* p) {
    uint32_t a;
    asm("{ .reg .u64 t; cvta.to.shared.u64 t, %1; cvt.u32.u64 %0, t; }"
        : "=r"(a) : "l"(p));
    return a;
}

__device__ __forceinline__ void cp16(uint32_t dst, const void* src) {
    asm volatile("cp.async.cg.shared.global [%0], [%1], 16;"
                 :: "r"(dst), "l"(src) : "memory");
}
#define CP_COMMIT() asm volatile("cp.async.commit_group;" ::: "memory")
#define CP_WAIT1()  asm volatile("cp.async.wait_group 1;" ::: "memory")
#define CP_WAIT0()  asm volatile("cp.async.wait_group 0;" ::: "memory")

__device__ __forceinline__ void ldm4(uint32_t* r, uint32_t addr) {
    asm volatile("ldmatrix.sync.aligned.m8n8.x4.shared.b16 {%0,%1,%2,%3}, [%4];"
                 : "=r"(r[0]), "=r"(r[1]), "=r"(r[2]), "=r"(r[3]) : "r"(addr));
}

#define MMA16816(cc, a0, a1, a2, a3, bb0, bb1) \
    asm("mma.sync.aligned.m16n8k16.row.col.f32.f16.f16.f32 " \
        "{%0,%1,%2,%3}, {%4,%5,%6,%7}, {%8,%9}, {%0,%1,%2,%3};" \
        : "+f"((cc)[0]), "+f"((cc)[1]), "+f"((cc)[2]), "+f"((cc)[3]) \
        : "r"(a0), "r"(a1), "r"(a2), "r"(a3), "r"(bb0), "r"(bb1))

// ---------------- fp16 double split --------------------------------------
// x = h0 + h1 + eps, |eps| <= ~2^-24 scale (h1 rounding / subnormal grid).
__device__ __forceinline__ void split2(float v, unsigned short& u0,
                                       unsigned short& u1) {
    __half h0 = __float2half_rn(v);
    float r1 = v - __half2float(h0);
    __half h1 = __float2half_rn(r1);
    memcpy(&u0, &h0, 2); memcpy(&u1, &h1, 2);
}
__device__ __forceinline__ uint32_t pack2(unsigned short lo, unsigned short hi) {
    return (uint32_t)lo | ((uint32_t)hi << 16);
}

// ---------------- kernel: split z (plain row-major) ----------------------
__global__ void __launch_bounds__(128)
vq_split_z(const float* __restrict__ z) {
    __shared__ float s[64][129];
    const int tile = blockIdx.x;
    const int n0 = tile * BM;
    const int b = n0 >> 12, p0 = n0 & 4095;
    const float* src = z + ((size_t)b * CDIM) * 4096 + p0;
    const int i = threadIdx.x;
#pragma unroll 8
    for (int c = 0; c < 64; c++) s[c][i] = src[(size_t)c * 4096 + i];
    __syncthreads();

#pragma unroll
    for (int j = 0; j < 8; j++) {
        unsigned short u0[8], u1[8];
#pragma unroll
        for (int q = 0; q < 8; q++) split2(s[j * 8 + q][i], u0[q], u1[q]);
        int idx = tile * 1024 + i * 8 + j;
        g_z0[idx] = make_uint4(pack2(u0[0], u0[1]), pack2(u0[2], u0[3]),
                               pack2(u0[4], u0[5]), pack2(u0[6], u0[7]));
        g_z1[idx] = make_uint4(pack2(u1[0], u1[1]), pack2(u1[2], u1[3]),
                               pack2(u1[4], u1[5]), pack2(u1[6], u1[7]));
    }
}

// ---------------- kernel: split codebook (plain row-major) ---------------
__global__ void __launch_bounds__(128)
vq_split_cb(const float* __restrict__ cb) {
    const int tile = blockIdx.x;
    const int i = threadIdx.x;
    float v[64];
    const float4* src = (const float4*)(cb + (size_t)(tile * BM + i) * CDIM);
#pragma unroll
    for (int t = 0; t < 16; t++) {
        float4 x = src[t];
        v[t * 4] = x.x; v[t * 4 + 1] = x.y; v[t * 4 + 2] = x.z; v[t * 4 + 3] = x.w;
    }
#pragma unroll
    for (int j = 0; j < 8; j++) {
        unsigned short u0[8], u1[8];
#pragma unroll
        for (int q = 0; q < 8; q++) split2(v[j * 8 + q], u0[q], u1[q]);
        int idx = tile * 1024 + i * 8 + j;
        g_e0[idx] = make_uint4(pack2(u0[0], u0[1]), pack2(u0[2], u0[3]),
                               pack2(u0[4], u0[5]), pack2(u0[6], u0[7]));
        g_e1[idx] = make_uint4(pack2(u1[0], u1[1]), pack2(u1[2], u1[3]),
                               pack2(u1[4], u1[5]), pack2(u1[6], u1[7]));
    }
}

__global__ void vq_init() {
    for (int i = threadIdx.x; i < N_CODES; i += blockDim.x) g_counts[i] = 0;
    if (threadIdx.x == 0) g_sumsq = 0.0f;
}

// ---------------- kernel: mma.sync GEMM + argmax + fused epilogue --------
// Emulated fp32 via fp16x2: logits = h0e0+h0e1+h1e0+h1e1 (error ~2^-24,
// same class as the proven bf16x6). 16 warps of 512 threads, warp tile
// 32x16, 64-code chunks, 2 CTAs/SM.
__global__ void __launch_bounds__(512, 2)
vq_mma(const float* __restrict__ cbf, float* __restrict__ out) {
    extern __shared__ char dsm[];
    const int tid = threadIdx.x;
    const int w = tid >> 5, lane = tid & 31;
    const int g = lane >> 2, q = lane & 3;
    const int mrow = lane & 7, quad = lane >> 3;
    const int wm = (w & 3) * 32, wn = (w >> 2) * 16;
    const int tile = blockIdx.x;

    const uint32_t sA = smem_u32(dsm);
    const uint32_t sB = sA + A_BYTES;

    // ldmatrix per-thread intra-plane offsets
    const uint32_t aoff = (uint32_t)(wm + mrow + 8 * (quad & 1)) * ROWB
                        + 16 * (quad >> 1);
    const uint32_t boff = (uint32_t)(wn + mrow + 8 * (quad >> 1)) * ROWB
                        + 16 * (quad & 1);

    // prologue: A tiles (2 planes) + B chunk 0 (one commit group)
    {
        const uint4* zs[2] = {g_z0 + tile * 1024, g_z1 + tile * 1024};
        for (int t = tid; t < 2048; t += 512) {
            int pl = t >> 10, rem = t & 1023, r = rem >> 3, j = rem & 7;
            cp16(sA + pl * PLANE_A + r * ROWB + j * 16, zs[pl] + rem);
        }
        const uint4* es[2] = {g_e0, g_e1};
        for (int t = tid; t < 1024; t += 512) {
            int pl = t >> 9, rem = t & 511, r = rem >> 3, j = rem & 7;
            cp16(sB + pl * PLANE_B + r * ROWB + j * 16, es[pl] + rem);
        }
        CP_COMMIT();
    }

    float bv[4];
    int   bi[4];
#pragma unroll
    for (int e = 0; e < 4; e++) { bv[e] = -3.4e38f; bi[e] = 0; }

    for (int ch = 0; ch < NCHUNK; ch++) {
        if (ch < NCHUNK - 1) {   // prefetch next B chunk into other buffer
            const uint4* es[2] = {g_e0 + (ch + 1) * 512, g_e1 + (ch + 1) * 512};
            uint32_t dstb = sB + ((ch + 1) & 1) * (2 * PLANE_B);
            for (int t = tid; t < 1024; t += 512) {
                int pl = t >> 9, rem = t & 511, r = rem >> 3, j = rem & 7;
                cp16(dstb + pl * PLANE_B + r * ROWB + j * 16, es[pl] + rem);
            }
            CP_COMMIT();
            CP_WAIT1();
        } else {
            CP_WAIT0();
        }
        __syncthreads();

        const uint32_t bB = sB + (ch & 1) * (2 * PLANE_B);

        float c[2][2][4];
#pragma unroll
        for (int mi = 0; mi < 2; mi++)
#pragma unroll
            for (int ni = 0; ni < 2; ni++)
#pragma unroll
                for (int e = 0; e < 4; e++) c[mi][ni][e] = 0.0f;

#pragma unroll
        for (int ks = 0; ks < 4; ks++) {
            const uint32_t koff = ks * 32;
            uint32_t B0[4], B1[4];
            ldm4(B0, bB + 0 * PLANE_B + boff + koff);
            ldm4(B1, bB + 1 * PLANE_B + boff + koff);

            uint32_t A[8];
            // h0: products with e0, e1
            ldm4(A,     sA + 0 * PLANE_A + aoff + koff);
            ldm4(A + 4, sA + 0 * PLANE_A + aoff + koff + 16 * ROWB);
#pragma unroll
            for (int mi = 0; mi < 2; mi++)
#pragma unroll
                for (int ni = 0; ni < 2; ni++) {
                    MMA16816(c[mi][ni], A[mi*4], A[mi*4+1], A[mi*4+2], A[mi*4+3],
                             B0[ni*2], B0[ni*2+1]);
                    MMA16816(c[mi][ni], A[mi*4], A[mi*4+1], A[mi*4+2], A[mi*4+3],
                             B1[ni*2], B1[ni*2+1]);
                }
            // h1: products with e0, e1
            ldm4(A,     sA + 1 * PLANE_A + aoff + koff);
            ldm4(A + 4, sA + 1 * PLANE_A + aoff + koff + 16 * ROWB);
#pragma unroll
            for (int mi = 0; mi < 2; mi++)
#pragma unroll
                for (int ni = 0; ni < 2; ni++) {
                    MMA16816(c[mi][ni], A[mi*4], A[mi*4+1], A[mi*4+2], A[mi*4+3],
                             B0[ni*2], B0[ni*2+1]);
                    MMA16816(c[mi][ni], A[mi*4], A[mi*4+1], A[mi*4+2], A[mi*4+3],
                             B1[ni*2], B1[ni*2+1]);
                }
        }

        // fold chunk into running argmax (ascending candidate order -> strict >)
        const int cb0 = ch * 64 + wn + 2 * q;
#pragma unroll
        for (int mi = 0; mi < 2; mi++) {
            const int lo = mi * 2, hi = mi * 2 + 1;
#pragma unroll
            for (int ni = 0; ni < 2; ni++) {
                int ce = cb0 + 8 * ni;
                if (c[mi][ni][0] > bv[lo]) { bv[lo] = c[mi][ni][0]; bi[lo] = ce; }
                if (c[mi][ni][1] > bv[lo]) { bv[lo] = c[mi][ni][1]; bi[lo] = ce + 1; }
                if (c[mi][ni][2] > bv[hi]) { bv[hi] = c[mi][ni][2]; bi[hi] = ce; }
                if (c[mi][ni][3] > bv[hi]) { bv[hi] = c[mi][ni][3]; bi[hi] = ce + 1; }
            }
        }
        __syncthreads();
    }

    // quad shuffle reduce (lanes sharing a row differ only in q)
#pragma unroll
    for (int e = 0; e < 4; e++) {
#pragma unroll
        for (int off = 1; off <= 2; off <<= 1) {
            float ov = __shfl_xor_sync(0xffffffffu, bv[e], off);
            int   oi = __shfl_xor_sync(0xffffffffu, bi[e], off);
            if (ov > bv[e] || (ov == bv[e] && oi < bi[e])) { bv[e] = ov; bi[e] = oi; }
        }
    }

    // reductions staged in dead B region (A planes still needed for zp)
    float* sval = (float*)(dsm + A_BYTES);             // [128][4]
    int*   sidx = (int*)(dsm + A_BYTES + 2048);        // [128][4]
    int*   ids  = (int*)(dsm + A_BYTES + 4096);        // [128]
    float* wsum = (float*)(dsm + A_BYTES + 4608);      // [16]
    float* zq   = (float*)(dsm + A_BYTES + 4672);      // [128][65] -> ends 74816
    if (q == 0) {
#pragma unroll
        for (int mi = 0; mi < 2; mi++)
#pragma unroll
            for (int h = 0; h < 2; h++) {
                int r = wm + 16 * mi + 8 * h + g;
                sval[r * 4 + (w >> 2)] = bv[mi * 2 + h];
                sidx[r * 4 + (w >> 2)] = bi[mi * 2 + h];
            }
    }
    __syncthreads();
    if (tid < 128) {
        float v = sval[tid * 4];
        int   i2 = sidx[tid * 4];
#pragma unroll
        for (int wg = 1; wg < 4; wg++) {
            float ov = sval[tid * 4 + wg];
            int   oi = sidx[tid * 4 + wg];
            if (ov > v || (ov == v && oi < i2)) { v = ov; i2 = oi; }
        }
        int n = tile * BM + tid;
        ids[tid] = i2;
        out[O_IDX + n] = (float)i2;
        atomicAdd(&g_counts[i2], 1);
    }
    __syncthreads();

    // gather codebook rows (fp32, L2-resident) into staging
    {
        int row = tid >> 2, h = tid & 3;
        const float4* src = (const float4*)(cbf + (size_t)ids[row] * CDIM + h * 16);
#pragma unroll
        for (int t = 0; t < 4; t++) {
            float4 vv = src[t];
            int c = h * 16 + t * 4;
            zq[row * 65 + c]     = vv.x;
            zq[row * 65 + c + 1] = vv.y;
            zq[row * 65 + c + 2] = vv.z;
            zq[row * 65 + c + 3] = vv.w;
        }
    }
    __syncthreads();

    // loss + transposed coalesced z_q store; zp = h0+h1 from smem planes
    {
        const int i = tid & 127;
        const int c0 = tid >> 7;          // 0..3
        const int b  = tile >> 5;
        const int p0 = (tile & 31) * BM;
        float* od = out + ((size_t)b * CDIM) * 4096 + p0;
        const char* a0 = dsm + 0 * PLANE_A + i * ROWB;
        const char* a1 = dsm + 1 * PLANE_A + i * ROWB;
        float lsum = 0.0f;
#pragma unroll
        for (int s = 0; s < 16; s++) {
            int c = c0 + 4 * s;
            float zp = __half2float(*(const __half*)(a0 + 2 * c))
                     + __half2float(*(const __half*)(a1 + 2 * c));
            float vq = zq[i * 65 + c];
            float d = vq - zp;
            lsum += d * d;
            od[(size_t)c * 4096 + i] = vq;
        }
        for (int o = 16; o > 0; o >>= 1)
            lsum += __shfl_down_sync(0xffffffffu, lsum, o);
        if (lane == 0) wsum[w] = lsum;
        __syncthreads();
        if (tid == 0) {
            float t = 0.0f;
#pragma unroll
            for (int ww = 0; ww < 16; ww++) t += wsum[ww];
            atomicAdd(&g_sumsq, t);
        }
    }
}

// ---------------- kernel: scalars ----------------------------------------
__global__ void vq_final(float* __restrict__ out) {
    __shared__ float red[256];
    const int tid = threadIdx.x;
    float h = 0.0f;
    for (int i = tid; i < N_CODES; i += 256) {
        float e = (float)g_counts[i] * (1.0f / 65536.0f);
        h -= e * logf(e + 1e-10f);
    }
    red[tid] = h;
    __syncthreads();
    for (int o = 128; o > 0; o >>= 1) {
        if (tid < o) red[tid] += red[tid + o];
        __syncthreads();
    }
    if (tid == 0) {
        out[O_LOSS] = 1.25f * g_sumsq / 4194304.0f;
        out[O_PERP] = expf(red[0]);
    }
}

extern "C" void kernel_launch(void* const* d_in, const int* in_sizes, int n_in,
                              void* d_out, int out_size) {
    const float* z  = (const float*)d_in[0];
    const float* cb = (const float*)d_in[1];
    if (n_in >= 2 && in_sizes[0] == N_CODES * CDIM) {
        z  = (const float*)d_in[1];
        cb = (const float*)d_in[0];
    }
    float* out = (float*)d_out;

    cudaFuncSetAttribute(vq_mma, cudaFuncAttributeMaxDynamicSharedMemorySize,
                         DSMEM_REQ);

    vq_split_z<<<N_TILES, 128>>>(z);
    vq_split_cb<<<E_TILES, 128>>>(cb);
    vq_init<<<1, 256>>>();
    vq_mma<<<N_TILES, 512, DSMEM_REQ>>>(cb, out);
    vq_final<<<1, 256>>>(out);
    (void)out_size;
}